// round 15
// baseline (speedup 1.0000x reference)
#include <cuda_runtime.h>
#include <math.h>
#include <stdint.h>

#define B 2
#define S 2048
#define H 8
#define D 64
#define DM 512
#define KP 72      // smem pad for qkv/out_proj GEMM kernels

// fragment-major K/V layout constants
#define TFRAG 132              // floats per (gid,t4) lane-block per tile (128 + 4 pad)
#define TILE_F (32 * TFRAG)    // 4224 floats per 64-row tile
#define BH_F (32 * TILE_F)     // floats per (b,h)

// Scratch (allocation-free rule: __device__ globals)
__device__ float g_Q[B * H * S * D];          // [b,h,s,d], tf32-rounded
__device__ float g_Kf[(size_t)B * H * BH_F];  // fragment-major, tf32-rounded
__device__ float g_Vf[(size_t)B * H * BH_F];  // fragment-major (V-specific layout)
__device__ float g_Ao[B * S * DM];            // [b,q, d*H+h]

__device__ __forceinline__ unsigned f2tf(float f) {
    unsigned u;
    asm("cvt.rna.tf32.f32 %0, %1;" : "=r"(u) : "f"(f));
    return u;
}

__device__ __forceinline__ void mma_tf32(float c[4], unsigned a0, unsigned a1,
                                         unsigned a2, unsigned a3,
                                         unsigned b0, unsigned b1) {
    asm volatile(
        "mma.sync.aligned.m16n8k8.row.col.f32.tf32.tf32.f32 "
        "{%0,%1,%2,%3}, {%4,%5,%6,%7}, {%8,%9}, {%0,%1,%2,%3};\n"
        : "+f"(c[0]), "+f"(c[1]), "+f"(c[2]), "+f"(c[3])
        : "r"(a0), "r"(a1), "r"(a2), "r"(a3), "r"(b0), "r"(b1));
}

__device__ __forceinline__ uint32_t smem_u32(const void* p) {
    return (uint32_t)__cvta_generic_to_shared(p);
}
__device__ __forceinline__ void cp16(uint32_t dst, const void* src) {
    asm volatile("cp.async.cg.shared.global [%0], [%1], 16;" :: "r"(dst), "l"(src));
}
#define CP_COMMIT() asm volatile("cp.async.commit_group;")
#define CP_WAIT1()  asm volatile("cp.async.wait_group 1;")

// ---------------------------------------------------------------------------
// Kernel 1: fused per-head QKV projection via tf32 mma.
// Q -> [b,h,s,d] tf32-rounded; K,V -> fragment-major (distinct layouts).
// ---------------------------------------------------------------------------
__global__ void __launch_bounds__(256) qkv_proj_kernel(
        const float* __restrict__ qin, const float* __restrict__ kin,
        const float* __restrict__ vin,
        const float* __restrict__ Wq, const float* __restrict__ bq,
        const float* __restrict__ Wk, const float* __restrict__ bk,
        const float* __restrict__ Wv, const float* __restrict__ bv) {
    extern __shared__ float sm[];
    float* Xs = sm;              // [128*KP]
    float* Ws = Xs + 128 * KP;   // [64*KP]
    float* bsh = Ws + 64 * KP;   // [64]

    int which = blockIdx.y;
    const float* X; const float* W; const float* bias; float* out;
    if (which == 0)      { X = qin; W = Wq; bias = bq; out = g_Q; }
    else if (which == 1) { X = kin; W = Wk; bias = bk; out = g_Kf; }
    else                 { X = vin; W = Wv; bias = bv; out = g_Vf; }

    int row0 = blockIdx.x * 128;
    int tid = threadIdx.x;

    for (int i = tid; i < 2048; i += 256) {
        int r = i >> 4, c = (i & 15) << 2;
        *(float4*)(Xs + r * KP + c) = *(const float4*)(X + (size_t)(row0 + r) * 64 + c);
    }
    for (int i = tid; i < 1024; i += 256) {
        int r = i >> 4, c = (i & 15) << 2;
        *(float4*)(Ws + r * KP + c) = *(const float4*)(W + (size_t)r * 64 + c);
    }
    if (tid < 64) bsh[tid] = bias[tid];
    __syncthreads();

    int w = tid >> 5, lane = tid & 31;
    int gid = lane >> 2, t4 = lane & 3;
    int rowA = (w * 16 + gid) * KP;

    float o[8][4] = {};
#pragma unroll
    for (int k8 = 0; k8 < 8; k8++) {
        int d0 = k8 * 8 + t4;
        unsigned a0 = f2tf(Xs[rowA + d0]);
        unsigned a1 = f2tf(Xs[rowA + 8 * KP + d0]);
        unsigned a2 = f2tf(Xs[rowA + d0 + 4]);
        unsigned a3 = f2tf(Xs[rowA + 8 * KP + d0 + 4]);
#pragma unroll
        for (int j = 0; j < 8; j++) {
            unsigned b0 = f2tf(Ws[(j * 8 + gid) * KP + d0]);
            unsigned b1 = f2tf(Ws[(j * 8 + gid) * KP + d0 + 4]);
            mma_tf32(o[j], a0, a1, a2, a3, b0, b1);
        }
    }

#pragma unroll
    for (int half = 0; half < 2; half++) {
        int r = row0 + w * 16 + gid + half * 8;   // r = (b*S+s)*H + h
        int h = r & (H - 1);
        int bsi = r >> 3;
        int bb = bsi >> 11;
        int ss = bsi & (S - 1);
        int bh = bb * H + h;
        if (which == 0) {
            float* op = out + (((size_t)bh) * S + ss) * D;
#pragma unroll
            for (int j = 0; j < 8; j++) {
                int e = j * 8 + 2 * t4;
                float2 v;
                v.x = __uint_as_float(f2tf(o[j][half * 2]     + bsh[e]));
                v.y = __uint_as_float(f2tf(o[j][half * 2 + 1] + bsh[e + 1]));
                *(float2*)(op + e) = v;
            }
        } else if (which == 1) {
            // K fragment-major: value K[n][e] ->
            //   lane = (n&7)*4 + (e&3), offset = (e>>3)*16 + 2*(n>>3) + ((e>>2)&1)
            int st = ss >> 6, n = ss & 63;
            float* base = out + (size_t)bh * BH_F + (size_t)st * TILE_F;
            int lane0 = ((n & 7) << 2) + 2 * (t4 & 1);   // e&3 = 2*(t4&1); e+1 -> +1
            int nofs = ((n >> 3) << 1) + (t4 >> 1);      // (e>>2)&1 = t4>>1 for both
#pragma unroll
            for (int j = 0; j < 8; j++) {
                int e = j * 8 + 2 * t4;
                int off = (j << 4) + nofs;               // e>>3 = j
                base[lane0 * TFRAG + off] =
                    __uint_as_float(f2tf(o[j][half * 2] + bsh[e]));
                base[(lane0 + 1) * TFRAG + off] =
                    __uint_as_float(f2tf(o[j][half * 2 + 1] + bsh[e + 1]));
            }
        } else {
            // V fragment-major: value V[n][e] ->
            //   lane = (e&7)*4 + (n&3), offset = (n>>3)*16 + 2*(e>>3) + ((n>>2)&1)
            int st = ss >> 6, n = ss & 63;
            float* base = out + (size_t)bh * BH_F + (size_t)st * TILE_F;
            int lane0 = (t4 << 3) + (n & 3);             // (e&7)=2*t4 -> lane 8*t4+(n&3)
            int off_base = ((n >> 3) << 4) + ((n >> 2) & 1);
#pragma unroll
            for (int j = 0; j < 8; j++) {
                int e = j * 8 + 2 * t4;
                int off = off_base + (j << 1);           // e>>3 = j
                base[lane0 * TFRAG + off] =
                    __uint_as_float(f2tf(o[j][half * 2] + bsh[e]));
                base[(lane0 + 4) * TFRAG + off] =        // e+1: (e+1)&7 = 2*t4+1
                    __uint_as_float(f2tf(o[j][half * 2 + 1] + bsh[e + 1]));
            }
        }
    }
}

// ---------------------------------------------------------------------------
// Kernel 2: flash attention, tf32 mma, fragment-major K/V via cp.async
// double buffering, Q fragments register-resident, P register-resident.
// 1 CTA = 128 q rows of one (b,h); 8 warps x 16 rows; kv tile = 64; occ 2.
// ---------------------------------------------------------------------------
__global__ void __launch_bounds__(256, 2) attn_kernel(const int* __restrict__ mask) {
    extern __shared__ float sm[];
    float* Ks0 = sm;                    // [2][TILE_F]
    float* Vs0 = Ks0 + 2 * TILE_F;      // [2][TILE_F]
    int*   mfs = (int*)(Vs0 + 2 * TILE_F);  // [2][64]

    int qt = blockIdx.x & 15;           // S/128 = 16 q-tiles
    int bh = blockIdx.x >> 4;
    int b = bh >> 3, h = bh & 7;
    int q0 = qt * 128;
    int tid = threadIdx.x;
    int w = tid >> 5, lane = tid & 31;
    int gid = lane >> 2, t4 = lane & 3;
    int srcA = t4 >> 1, srcB = srcA + 2;
    bool odd = (t4 & 1) != 0;

    const float* Qg = g_Q + ((size_t)bh * S + q0) * D;
    const float* Kf = g_Kf + (size_t)bh * BH_F;
    const float* Vf = g_Vf + (size_t)bh * BH_F;
    const int* mg = mask + b * S;

    // Q as register-resident tf32 A-fragments (pre-rounded in g_Q)
    unsigned qa[8][4];
    {
        int r0 = w * 16 + gid;
#pragma unroll
        for (int k8 = 0; k8 < 8; k8++) {
            int d0 = k8 * 8 + t4;
            qa[k8][0] = __float_as_uint(Qg[(size_t)r0 * D + d0]);
            qa[k8][1] = __float_as_uint(Qg[(size_t)(r0 + 8) * D + d0]);
            qa[k8][2] = __float_as_uint(Qg[(size_t)r0 * D + d0 + 4]);
            qa[k8][3] = __float_as_uint(Qg[(size_t)(r0 + 8) * D + d0 + 4]);
        }
    }

    // prefetch tile 0
    for (int i = tid; i < TILE_F / 4; i += 256) {
        cp16(smem_u32(Ks0 + i * 4), Kf + (size_t)i * 4);
        cp16(smem_u32(Vs0 + i * 4), Vf + (size_t)i * 4);
    }
    if (tid < 16) cp16(smem_u32(mfs + tid * 4), mg + tid * 4);
    CP_COMMIT();

    float o[8][4] = {};
    float m0 = -INFINITY, m1 = -INFINITY;
    float l0 = 0.0f, l1 = 0.0f;

    for (int kt = 0; kt < S / 64; kt++) {
        int buf = kt & 1;
        const float* Kt = Ks0 + buf * TILE_F + lane * TFRAG;
        const float* Vt = Vs0 + buf * TILE_F + lane * TFRAG;
        int* mf = mfs + buf * 64;

        // prefetch next tile into the other buffer
        if (kt + 1 < S / 64) {
            int nb = buf ^ 1;
            const float* kp = Kf + (size_t)(kt + 1) * TILE_F;
            const float* vp = Vf + (size_t)(kt + 1) * TILE_F;
            float* Kn = Ks0 + nb * TILE_F;
            float* Vn = Vs0 + nb * TILE_F;
            for (int i = tid; i < TILE_F / 4; i += 256) {
                cp16(smem_u32(Kn + i * 4), kp + (size_t)i * 4);
                cp16(smem_u32(Vn + i * 4), vp + (size_t)i * 4);
            }
            if (tid < 16) cp16(smem_u32(mfs + nb * 64 + tid * 4),
                               mg + (kt + 1) * 64 + tid * 4);
        }
        CP_COMMIT();
        CP_WAIT1();
        __syncthreads();   // tile kt visible to all threads

        // ---- QK^T: S(16x64) per warp; K frags as LDS.128, no cvt ----
        float c[8][4] = {};
#pragma unroll
        for (int k8 = 0; k8 < 8; k8++) {
            const float4* kf = (const float4*)(Kt + k8 * 16);
            float4 f0 = kf[0], f1 = kf[1], f2 = kf[2], f3 = kf[3];
            mma_tf32(c[0], qa[k8][0], qa[k8][1], qa[k8][2], qa[k8][3],
                     __float_as_uint(f0.x), __float_as_uint(f0.y));
            mma_tf32(c[1], qa[k8][0], qa[k8][1], qa[k8][2], qa[k8][3],
                     __float_as_uint(f0.z), __float_as_uint(f0.w));
            mma_tf32(c[2], qa[k8][0], qa[k8][1], qa[k8][2], qa[k8][3],
                     __float_as_uint(f1.x), __float_as_uint(f1.y));
            mma_tf32(c[3], qa[k8][0], qa[k8][1], qa[k8][2], qa[k8][3],
                     __float_as_uint(f1.z), __float_as_uint(f1.w));
            mma_tf32(c[4], qa[k8][0], qa[k8][1], qa[k8][2], qa[k8][3],
                     __float_as_uint(f2.x), __float_as_uint(f2.y));
            mma_tf32(c[5], qa[k8][0], qa[k8][1], qa[k8][2], qa[k8][3],
                     __float_as_uint(f2.z), __float_as_uint(f2.w));
            mma_tf32(c[6], qa[k8][0], qa[k8][1], qa[k8][2], qa[k8][3],
                     __float_as_uint(f3.x), __float_as_uint(f3.y));
            mma_tf32(c[7], qa[k8][0], qa[k8][1], qa[k8][2], qa[k8][3],
                     __float_as_uint(f3.z), __float_as_uint(f3.w));
        }

        // ---- C-layout -> A-layout (quad shuffles) + mask + scale ----
#pragma unroll
        for (int j = 0; j < 8; j++) {
            float l00 = __shfl_sync(0xffffffffu, c[j][0], srcA, 4);
            float l01 = __shfl_sync(0xffffffffu, c[j][1], srcA, 4);
            float l20 = __shfl_sync(0xffffffffu, c[j][2], srcA, 4);
            float l21 = __shfl_sync(0xffffffffu, c[j][3], srcA, 4);
            float h00 = __shfl_sync(0xffffffffu, c[j][0], srcB, 4);
            float h01 = __shfl_sync(0xffffffffu, c[j][1], srcB, 4);
            float h20 = __shfl_sync(0xffffffffu, c[j][2], srcB, 4);
            float h21 = __shfl_sync(0xffffffffu, c[j][3], srcB, 4);
            float a0 = odd ? l01 : l00;
            float a1 = odd ? l21 : l20;
            float a2 = odd ? h01 : h00;
            float a3 = odd ? h21 : h20;
            bool f0 = mf[j * 8 + t4] != 0;
            bool f4 = mf[j * 8 + t4 + 4] != 0;
            c[j][0] = f0 ? a0 * 0.25f : -2.5e19f;
            c[j][1] = f0 ? a1 * 0.25f : -2.5e19f;
            c[j][2] = f4 ? a2 * 0.25f : -2.5e19f;
            c[j][3] = f4 ? a3 * 0.25f : -2.5e19f;
        }

        // ---- online softmax (row gid: regs 0,2; row gid+8: regs 1,3) ----
        float rm0 = -INFINITY, rm1 = -INFINITY;
#pragma unroll
        for (int j = 0; j < 8; j++) {
            rm0 = fmaxf(rm0, fmaxf(c[j][0], c[j][2]));
            rm1 = fmaxf(rm1, fmaxf(c[j][1], c[j][3]));
        }
        rm0 = fmaxf(rm0, __shfl_xor_sync(0xffffffffu, rm0, 1, 4));
        rm0 = fmaxf(rm0, __shfl_xor_sync(0xffffffffu, rm0, 2, 4));
        rm1 = fmaxf(rm1, __shfl_xor_sync(0xffffffffu, rm1, 1, 4));
        rm1 = fmaxf(rm1, __shfl_xor_sync(0xffffffffu, rm1, 2, 4));
        float mn0 = fmaxf(m0, rm0), mn1 = fmaxf(m1, rm1);
        float cr0 = __expf(m0 - mn0), cr1 = __expf(m1 - mn1);
        m0 = mn0; m1 = mn1;

        float s0 = 0.0f, s1 = 0.0f;
#pragma unroll
        for (int j = 0; j < 8; j++) {
            float p0 = __uint_as_float(f2tf(__expf(c[j][0] - mn0)));
            float p1 = __uint_as_float(f2tf(__expf(c[j][1] - mn1)));
            float p2 = __uint_as_float(f2tf(__expf(c[j][2] - mn0)));
            float p3 = __uint_as_float(f2tf(__expf(c[j][3] - mn1)));
            c[j][0] = p0; c[j][1] = p1; c[j][2] = p2; c[j][3] = p3;
            s0 += p0 + p2;
            s1 += p1 + p3;
        }
        s0 += __shfl_xor_sync(0xffffffffu, s0, 1, 4);
        s0 += __shfl_xor_sync(0xffffffffu, s0, 2, 4);
        s1 += __shfl_xor_sync(0xffffffffu, s1, 1, 4);
        s1 += __shfl_xor_sync(0xffffffffu, s1, 2, 4);
        l0 = l0 * cr0 + s0;
        l1 = l1 * cr1 + s1;
#pragma unroll
        for (int j = 0; j < 8; j++) {
            o[j][0] *= cr0;  o[j][1] *= cr0;
            o[j][2] *= cr1;  o[j][3] *= cr1;
        }

        // ---- PV: O += P.V ; V frags as LDS.128, no cvt ----
#pragma unroll
        for (int k8 = 0; k8 < 8; k8++) {
            unsigned a0 = __float_as_uint(c[k8][0]);
            unsigned a1 = __float_as_uint(c[k8][1]);
            unsigned a2 = __float_as_uint(c[k8][2]);
            unsigned a3 = __float_as_uint(c[k8][3]);
            const float4* vf = (const float4*)(Vt + k8 * 16);
            float4 f0 = vf[0], f1 = vf[1], f2 = vf[2], f3 = vf[3];
            mma_tf32(o[0], a0, a1, a2, a3, __float_as_uint(f0.x), __float_as_uint(f0.y));
            mma_tf32(o[1], a0, a1, a2, a3, __float_as_uint(f0.z), __float_as_uint(f0.w));
            mma_tf32(o[2], a0, a1, a2, a3, __float_as_uint(f1.x), __float_as_uint(f1.y));
            mma_tf32(o[3], a0, a1, a2, a3, __float_as_uint(f1.z), __float_as_uint(f1.w));
            mma_tf32(o[4], a0, a1, a2, a3, __float_as_uint(f2.x), __float_as_uint(f2.y));
            mma_tf32(o[5], a0, a1, a2, a3, __float_as_uint(f2.z), __float_as_uint(f2.w));
            mma_tf32(o[6], a0, a1, a2, a3, __float_as_uint(f3.x), __float_as_uint(f3.y));
            mma_tf32(o[7], a0, a1, a2, a3, __float_as_uint(f3.z), __float_as_uint(f3.w));
        }
        __syncthreads();   // all warps done with buf before next prefetch hits it
    }

    // ---- write Ao[b, q, d*H + h] ----
    float inv0 = 1.0f / l0, inv1 = 1.0f / l1;
    int qr0 = q0 + w * 16 + gid;
    float* ob0 = g_Ao + ((size_t)(b * S + qr0)) * DM + h;
    float* ob1 = g_Ao + ((size_t)(b * S + qr0 + 8)) * DM + h;
#pragma unroll
    for (int j = 0; j < 8; j++) {
        int d0 = j * 8 + 2 * t4;
        ob0[d0 * H]       = o[j][0] * inv0;
        ob0[(d0 + 1) * H] = o[j][1] * inv0;
        ob1[d0 * H]       = o[j][2] * inv1;
        ob1[(d0 + 1) * H] = o[j][3] * inv1;
    }
}

// ---------------------------------------------------------------------------
// Kernel 3: output projection  Y = Ao @ Wo^T + bo via tf32 mma.
// ---------------------------------------------------------------------------
__global__ void __launch_bounds__(256) out_proj_kernel(
        const float* __restrict__ Wo, const float* __restrict__ bo,
        float* __restrict__ Y) {
    extern __shared__ float sm[];
    float* As = sm;              // [128*KP]
    float* Bs = As + 128 * KP;   // [64*KP]

    int row0 = blockIdx.x * 128;
    int col0 = blockIdx.y * 64;
    int tid = threadIdx.x;
    int w = tid >> 5, lane = tid & 31;
    int gid = lane >> 2, t4 = lane & 3;
    int rowA = (w * 16 + gid) * KP;

    float o[8][4] = {};
    for (int kc = 0; kc < DM / 64; kc++) {
        __syncthreads();
        for (int i = tid; i < 2048; i += 256) {
            int r = i >> 4, c = (i & 15) << 2;
            *(float4*)(As + r * KP + c) =
                *(const float4*)(g_Ao + (size_t)(row0 + r) * DM + kc * 64 + c);
        }
        for (int i = tid; i < 1024; i += 256) {
            int r = i >> 4, c = (i & 15) << 2;
            *(float4*)(Bs + r * KP + c) =
                *(const float4*)(Wo + (size_t)(col0 + r) * DM + kc * 64 + c);
        }
        __syncthreads();
#pragma unroll
        for (int k8 = 0; k8 < 8; k8++) {
            int d0 = k8 * 8 + t4;
            unsigned a0 = f2tf(As[rowA + d0]);
            unsigned a1 = f2tf(As[rowA + 8 * KP + d0]);
            unsigned a2 = f2tf(As[rowA + d0 + 4]);
            unsigned a3 = f2tf(As[rowA + 8 * KP + d0 + 4]);
#pragma unroll
            for (int j = 0; j < 8; j++) {
                unsigned b0 = f2tf(Bs[(j * 8 + gid) * KP + d0]);
                unsigned b1 = f2tf(Bs[(j * 8 + gid) * KP + d0 + 4]);
                mma_tf32(o[j], a0, a1, a2, a3, b0, b1);
            }
        }
    }

#pragma unroll
    for (int half = 0; half < 2; half++) {
        int r = row0 + w * 16 + gid + half * 8;
#pragma unroll
        for (int j = 0; j < 8; j++) {
            int cidx = col0 + j * 8 + 2 * t4;
            float2 v;
            v.x = o[j][half * 2]     + bo[cidx];
            v.y = o[j][half * 2 + 1] + bo[cidx + 1];
            *(float2*)(Y + (size_t)r * DM + cidx) = v;
        }
    }
}

// ---------------------------------------------------------------------------
extern "C" void kernel_launch(void* const* d_in, const int* in_sizes, int n_in,
                              void* d_out, int out_size) {
    const float* q  = (const float*)d_in[0];
    const float* k  = (const float*)d_in[1];
    const float* v  = (const float*)d_in[2];
    const float* Wq = (const float*)d_in[3];
    const float* bq = (const float*)d_in[4];
    const float* Wk = (const float*)d_in[5];
    const float* bk = (const float*)d_in[6];
    const float* Wv = (const float*)d_in[7];
    const float* bv = (const float*)d_in[8];
    const float* Wo = (const float*)d_in[9];
    const float* bo = (const float*)d_in[10];
    const int* mask = (const int*)d_in[11];
    float* out = (float*)d_out;

    // 1) QKV projections: 256 row-tiles x 3 matrices
    int qkv_smem = (128 * KP + 64 * KP + 64) * (int)sizeof(float);
    cudaFuncSetAttribute(qkv_proj_kernel,
                         cudaFuncAttributeMaxDynamicSharedMemorySize, qkv_smem);
    qkv_proj_kernel<<<dim3(B * S * H / 128, 3), 256, qkv_smem>>>(
        q, k, v, Wq, bq, Wk, bk, Wv, bv);

    // 2) flash attention: 256 blocks, 2 CTAs/SM, ~66.5KB smem
    int attn_smem = (4 * TILE_F) * (int)sizeof(float) + 2 * 64 * (int)sizeof(int);
    cudaFuncSetAttribute(attn_kernel,
                         cudaFuncAttributeMaxDynamicSharedMemorySize, attn_smem);
    attn_kernel<<<B * H * (S / 128), 256, attn_smem>>>(mask);

    // 3) output projection
    int op_smem = (128 * KP + 64 * KP) * (int)sizeof(float);
    cudaFuncSetAttribute(out_proj_kernel,
                         cudaFuncAttributeMaxDynamicSharedMemorySize, op_smem);
    out_proj_kernel<<<dim3(B * S / 128, DM / 64), 256, op_smem>>>(Wo, bo, out);
}

// round 16
// speedup vs baseline: 1.3896x; 1.3896x over previous
#include <cuda_runtime.h>
#include <math.h>
#include <stdint.h>

#define B 2
#define S 2048
#define H 8
#define D 64
#define DM 512
#define KP 72   // smem pad: both (8*gid+t4) and (8*t4+gid) frag patterns conflict-free

// Scratch (allocation-free rule: __device__ globals)
__device__ float g_Q[B * H * S * D];   // [b,h,s,d], tf32-rounded
__device__ float g_K[B * H * S * D];   // [b,h,s,d], tf32-rounded
__device__ float g_V[B * H * S * D];   // [b,h,s,d], tf32-rounded
__device__ float g_Ao[B * S * DM];     // [b,q, d*H+h], tf32-rounded

__device__ __forceinline__ unsigned f2tf(float f) {
    unsigned u;
    asm("cvt.rna.tf32.f32 %0, %1;" : "=r"(u) : "f"(f));
    return u;
}

__device__ __forceinline__ void mma_tf32(float c[4], unsigned a0, unsigned a1,
                                         unsigned a2, unsigned a3,
                                         unsigned b0, unsigned b1) {
    asm volatile(
        "mma.sync.aligned.m16n8k8.row.col.f32.tf32.tf32.f32 "
        "{%0,%1,%2,%3}, {%4,%5,%6,%7}, {%8,%9}, {%0,%1,%2,%3};\n"
        : "+f"(c[0]), "+f"(c[1]), "+f"(c[2]), "+f"(c[3])
        : "r"(a0), "r"(a1), "r"(a2), "r"(a3), "r"(b0), "r"(b1));
}

__device__ __forceinline__ uint32_t smem_u32(const void* p) {
    return (uint32_t)__cvta_generic_to_shared(p);
}
__device__ __forceinline__ void cp16(uint32_t dst, const void* src) {
    asm volatile("cp.async.cg.shared.global [%0], [%1], 16;" :: "r"(dst), "l"(src));
}
#define CP_COMMIT() asm volatile("cp.async.commit_group;")
#define CP_WAIT1()  asm volatile("cp.async.wait_group 1;")

// ---------------------------------------------------------------------------
// Kernel 1: fused per-head QKV projection via tf32 mma.
// All outputs row-major [b,h,s,e], tf32-rounded at write (coalesced float2).
// ---------------------------------------------------------------------------
__global__ void __launch_bounds__(256) qkv_proj_kernel(
        const float* __restrict__ qin, const float* __restrict__ kin,
        const float* __restrict__ vin,
        const float* __restrict__ Wq, const float* __restrict__ bq,
        const float* __restrict__ Wk, const float* __restrict__ bk,
        const float* __restrict__ Wv, const float* __restrict__ bv) {
    extern __shared__ float sm[];
    float* Xs = sm;              // [128*KP]
    float* Ws = Xs + 128 * KP;   // [64*KP]
    float* bsh = Ws + 64 * KP;   // [64]

    int which = blockIdx.y;
    const float* X; const float* W; const float* bias; float* out;
    if (which == 0)      { X = qin; W = Wq; bias = bq; out = g_Q; }
    else if (which == 1) { X = kin; W = Wk; bias = bk; out = g_K; }
    else                 { X = vin; W = Wv; bias = bv; out = g_V; }

    int row0 = blockIdx.x * 128;
    int tid = threadIdx.x;

    for (int i = tid; i < 2048; i += 256) {
        int r = i >> 4, c = (i & 15) << 2;
        *(float4*)(Xs + r * KP + c) = *(const float4*)(X + (size_t)(row0 + r) * 64 + c);
    }
    for (int i = tid; i < 1024; i += 256) {
        int r = i >> 4, c = (i & 15) << 2;
        *(float4*)(Ws + r * KP + c) = *(const float4*)(W + (size_t)r * 64 + c);
    }
    if (tid < 64) bsh[tid] = bias[tid];
    __syncthreads();

    int w = tid >> 5, lane = tid & 31;
    int gid = lane >> 2, t4 = lane & 3;
    int rowA = (w * 16 + gid) * KP;

    float o[8][4] = {};
#pragma unroll
    for (int k8 = 0; k8 < 8; k8++) {
        int d0 = k8 * 8 + t4;
        unsigned a0 = f2tf(Xs[rowA + d0]);
        unsigned a1 = f2tf(Xs[rowA + 8 * KP + d0]);
        unsigned a2 = f2tf(Xs[rowA + d0 + 4]);
        unsigned a3 = f2tf(Xs[rowA + 8 * KP + d0 + 4]);
#pragma unroll
        for (int j = 0; j < 8; j++) {
            unsigned b0 = f2tf(Ws[(j * 8 + gid) * KP + d0]);
            unsigned b1 = f2tf(Ws[(j * 8 + gid) * KP + d0 + 4]);
            mma_tf32(o[j], a0, a1, a2, a3, b0, b1);
        }
    }

    // epilogue: tf32-round at write so attention never converts
#pragma unroll
    for (int half = 0; half < 2; half++) {
        int r = row0 + w * 16 + gid + half * 8;   // r = (b*S+s)*H + h
        int h = r & (H - 1);
        int bsi = r >> 3;
        int bb = bsi >> 11;
        int ss = bsi & (S - 1);
        float* op = out + (((size_t)(bb * H + h)) * S + ss) * D;
#pragma unroll
        for (int j = 0; j < 8; j++) {
            int e = j * 8 + 2 * t4;
            float2 v;
            v.x = __uint_as_float(f2tf(o[j][half * 2]     + bsh[e]));
            v.y = __uint_as_float(f2tf(o[j][half * 2 + 1] + bsh[e + 1]));
            *(float2*)(op + e) = v;
        }
    }
}

// ---------------------------------------------------------------------------
// Kernel 2: flash attention, tf32 mma, cp.async double-buffered K/V,
// register-resident P via width-4 shuffle layout conversion.
// All smem tiles hold pre-rounded tf32 values -> zero cvt in the loop.
// 1 CTA = 128 q rows of one (b,h); 8 warps x 16 rows; kv tile = 64; occ 2.
// ---------------------------------------------------------------------------
__global__ void __launch_bounds__(256, 2) attn_kernel(const int* __restrict__ mask) {
    extern __shared__ float sm[];
    float* Qs  = sm;                    // [128*KP] tf32-rounded f32
    float* Ks0 = Qs + 128 * KP;         // [2][64*KP]
    float* Vs0 = Ks0 + 2 * 64 * KP;     // [2][64*KP]
    int*   mfs = (int*)(Vs0 + 2 * 64 * KP);  // [2][64]

    int qt = blockIdx.x & 15;           // S/128 = 16 q-tiles
    int bh = blockIdx.x >> 4;
    int b = bh >> 3, h = bh & 7;
    int q0 = qt * 128;
    int tid = threadIdx.x;
    int w = tid >> 5, lane = tid & 31;
    int gid = lane >> 2, t4 = lane & 3;
    int srcA = t4 >> 1, srcB = srcA + 2;
    bool odd = (t4 & 1) != 0;

    const float* Qg = g_Q + ((size_t)bh * S + q0) * D;
    const float* Kg = g_K + (size_t)bh * S * D;
    const float* Vg = g_V + (size_t)bh * S * D;
    const int* mg = mask + b * S;

    // group 0: Q + K/V tile 0 + mask 0
    for (int i = tid; i < 2048; i += 256) {
        int r = i >> 4, c = (i & 15) << 2;
        cp16(smem_u32(Qs + r * KP + c), Qg + (size_t)r * 64 + c);
    }
    for (int i = tid; i < 1024; i += 256) {
        int r = i >> 4, c = (i & 15) << 2;
        cp16(smem_u32(Ks0 + r * KP + c), Kg + (size_t)r * 64 + c);
        cp16(smem_u32(Vs0 + r * KP + c), Vg + (size_t)r * 64 + c);
    }
    if (tid < 16) cp16(smem_u32(mfs + tid * 4), mg + tid * 4);
    CP_COMMIT();

    float o[8][4] = {};
    float m0 = -INFINITY, m1 = -INFINITY;
    float l0 = 0.0f, l1 = 0.0f;
    int rowA = (w * 16 + gid) * KP;

    for (int kt = 0; kt < S / 64; kt++) {
        int buf = kt & 1;
        float* Ks = Ks0 + buf * 64 * KP;
        float* Vs = Vs0 + buf * 64 * KP;
        int* mf = mfs + buf * 64;

        // prefetch next tile into the other buffer
        if (kt + 1 < S / 64) {
            int nb = buf ^ 1;
            const float* kp = Kg + (size_t)(kt + 1) * 64 * D;
            const float* vp = Vg + (size_t)(kt + 1) * 64 * D;
            float* Kn = Ks0 + nb * 64 * KP;
            float* Vn = Vs0 + nb * 64 * KP;
            for (int i = tid; i < 1024; i += 256) {
                int r = i >> 4, c = (i & 15) << 2;
                cp16(smem_u32(Kn + r * KP + c), kp + (size_t)r * 64 + c);
                cp16(smem_u32(Vn + r * KP + c), vp + (size_t)r * 64 + c);
            }
            if (tid < 16) cp16(smem_u32(mfs + nb * 64 + tid * 4),
                               mg + (kt + 1) * 64 + tid * 4);
        }
        CP_COMMIT();
        CP_WAIT1();
        __syncthreads();   // tile kt visible to all threads

        // ---- QK^T: S(16x64) per warp; no cvt (values pre-rounded) ----
        float c[8][4] = {};
#pragma unroll
        for (int k8 = 0; k8 < 8; k8++) {
            int d0 = k8 * 8 + t4;
            unsigned a0 = __float_as_uint(Qs[rowA + d0]);
            unsigned a1 = __float_as_uint(Qs[rowA + 8 * KP + d0]);
            unsigned a2 = __float_as_uint(Qs[rowA + d0 + 4]);
            unsigned a3 = __float_as_uint(Qs[rowA + 8 * KP + d0 + 4]);
#pragma unroll
            for (int j = 0; j < 8; j++) {
                unsigned b0 = __float_as_uint(Ks[(j * 8 + gid) * KP + d0]);
                unsigned b1 = __float_as_uint(Ks[(j * 8 + gid) * KP + d0 + 4]);
                mma_tf32(c[j], a0, a1, a2, a3, b0, b1);
            }
        }

        // ---- C-layout -> A-layout (quad shuffles) + mask + scale ----
        // After this: c[j][0]=row gid col j*8+t4, c[j][1]=row gid+8 col j*8+t4,
        //             c[j][2]=row gid col +4,     c[j][3]=row gid+8 col +4.
#pragma unroll
        for (int j = 0; j < 8; j++) {
            float l00 = __shfl_sync(0xffffffffu, c[j][0], srcA, 4);
            float l01 = __shfl_sync(0xffffffffu, c[j][1], srcA, 4);
            float l20 = __shfl_sync(0xffffffffu, c[j][2], srcA, 4);
            float l21 = __shfl_sync(0xffffffffu, c[j][3], srcA, 4);
            float h00 = __shfl_sync(0xffffffffu, c[j][0], srcB, 4);
            float h01 = __shfl_sync(0xffffffffu, c[j][1], srcB, 4);
            float h20 = __shfl_sync(0xffffffffu, c[j][2], srcB, 4);
            float h21 = __shfl_sync(0xffffffffu, c[j][3], srcB, 4);
            float a0 = odd ? l01 : l00;
            float a1 = odd ? l21 : l20;
            float a2 = odd ? h01 : h00;
            float a3 = odd ? h21 : h20;
            bool f0 = mf[j * 8 + t4] != 0;
            bool f4 = mf[j * 8 + t4 + 4] != 0;
            c[j][0] = f0 ? a0 * 0.25f : -2.5e19f;
            c[j][1] = f0 ? a1 * 0.25f : -2.5e19f;
            c[j][2] = f4 ? a2 * 0.25f : -2.5e19f;
            c[j][3] = f4 ? a3 * 0.25f : -2.5e19f;
        }

        // ---- online softmax (row gid: regs 0,2; row gid+8: regs 1,3) ----
        float rm0 = -INFINITY, rm1 = -INFINITY;
#pragma unroll
        for (int j = 0; j < 8; j++) {
            rm0 = fmaxf(rm0, fmaxf(c[j][0], c[j][2]));
            rm1 = fmaxf(rm1, fmaxf(c[j][1], c[j][3]));
        }
        rm0 = fmaxf(rm0, __shfl_xor_sync(0xffffffffu, rm0, 1, 4));
        rm0 = fmaxf(rm0, __shfl_xor_sync(0xffffffffu, rm0, 2, 4));
        rm1 = fmaxf(rm1, __shfl_xor_sync(0xffffffffu, rm1, 1, 4));
        rm1 = fmaxf(rm1, __shfl_xor_sync(0xffffffffu, rm1, 2, 4));
        float mn0 = fmaxf(m0, rm0), mn1 = fmaxf(m1, rm1);
        float cr0 = __expf(m0 - mn0), cr1 = __expf(m1 - mn1);
        m0 = mn0; m1 = mn1;

        float s0 = 0.0f, s1 = 0.0f;
#pragma unroll
        for (int j = 0; j < 8; j++) {
            float p0 = __uint_as_float(f2tf(__expf(c[j][0] - mn0)));
            float p1 = __uint_as_float(f2tf(__expf(c[j][1] - mn1)));
            float p2 = __uint_as_float(f2tf(__expf(c[j][2] - mn0)));
            float p3 = __uint_as_float(f2tf(__expf(c[j][3] - mn1)));
            c[j][0] = p0; c[j][1] = p1; c[j][2] = p2; c[j][3] = p3;
            s0 += p0 + p2;
            s1 += p1 + p3;
        }
        s0 += __shfl_xor_sync(0xffffffffu, s0, 1, 4);
        s0 += __shfl_xor_sync(0xffffffffu, s0, 2, 4);
        s1 += __shfl_xor_sync(0xffffffffu, s1, 1, 4);
        s1 += __shfl_xor_sync(0xffffffffu, s1, 2, 4);
        l0 = l0 * cr0 + s0;
        l1 = l1 * cr1 + s1;
#pragma unroll
        for (int j = 0; j < 8; j++) {
            o[j][0] *= cr0;  o[j][1] *= cr0;
            o[j][2] *= cr1;  o[j][3] *= cr1;
        }

        // ---- PV: O += P.V ; P A-frags straight from registers; no cvt ----
#pragma unroll
        for (int k8 = 0; k8 < 8; k8++) {
            unsigned a0 = __float_as_uint(c[k8][0]);
            unsigned a1 = __float_as_uint(c[k8][1]);
            unsigned a2 = __float_as_uint(c[k8][2]);
            unsigned a3 = __float_as_uint(c[k8][3]);
#pragma unroll
            for (int j = 0; j < 8; j++) {
                unsigned b0 = __float_as_uint(Vs[(k8 * 8 + t4) * KP + j * 8 + gid]);
                unsigned b1 = __float_as_uint(Vs[(k8 * 8 + t4 + 4) * KP + j * 8 + gid]);
                mma_tf32(o[j], a0, a1, a2, a3, b0, b1);
            }
        }
        __syncthreads();   // all warps done with buf before next prefetch hits it
    }

    // ---- write Ao[b, q, d*H + h], tf32-rounded for out_proj ----
    float inv0 = 1.0f / l0, inv1 = 1.0f / l1;
    int qr0 = q0 + w * 16 + gid;
    float* ob0 = g_Ao + ((size_t)(b * S + qr0)) * DM + h;
    float* ob1 = g_Ao + ((size_t)(b * S + qr0 + 8)) * DM + h;
#pragma unroll
    for (int j = 0; j < 8; j++) {
        int d0 = j * 8 + 2 * t4;
        ob0[d0 * H]       = __uint_as_float(f2tf(o[j][0] * inv0));
        ob0[(d0 + 1) * H] = __uint_as_float(f2tf(o[j][1] * inv0));
        ob1[d0 * H]       = __uint_as_float(f2tf(o[j][2] * inv1));
        ob1[(d0 + 1) * H] = __uint_as_float(f2tf(o[j][3] * inv1));
    }
}

// ---------------------------------------------------------------------------
// Kernel 3: output projection  Y = Ao @ Wo^T + bo via tf32 mma.
// A-side pre-rounded (no cvt); W-side cvt at use.
// ---------------------------------------------------------------------------
__global__ void __launch_bounds__(256) out_proj_kernel(
        const float* __restrict__ Wo, const float* __restrict__ bo,
        float* __restrict__ Y) {
    extern __shared__ float sm[];
    float* As = sm;              // [128*KP]
    float* Bs = As + 128 * KP;   // [64*KP]

    int row0 = blockIdx.x * 128;
    int col0 = blockIdx.y * 64;
    int tid = threadIdx.x;
    int w = tid >> 5, lane = tid & 31;
    int gid = lane >> 2, t4 = lane & 3;
    int rowA = (w * 16 + gid) * KP;

    float o[8][4] = {};
    for (int kc = 0; kc < DM / 64; kc++) {
        __syncthreads();
        for (int i = tid; i < 2048; i += 256) {
            int r = i >> 4, c = (i & 15) << 2;
            *(float4*)(As + r * KP + c) =
                *(const float4*)(g_Ao + (size_t)(row0 + r) * DM + kc * 64 + c);
        }
        for (int i = tid; i < 1024; i += 256) {
            int r = i >> 4, c = (i & 15) << 2;
            *(float4*)(Bs + r * KP + c) =
                *(const float4*)(Wo + (size_t)(col0 + r) * DM + kc * 64 + c);
        }
        __syncthreads();
#pragma unroll
        for (int k8 = 0; k8 < 8; k8++) {
            int d0 = k8 * 8 + t4;
            unsigned a0 = __float_as_uint(As[rowA + d0]);
            unsigned a1 = __float_as_uint(As[rowA + 8 * KP + d0]);
            unsigned a2 = __float_as_uint(As[rowA + d0 + 4]);
            unsigned a3 = __float_as_uint(As[rowA + 8 * KP + d0 + 4]);
#pragma unroll
            for (int j = 0; j < 8; j++) {
                unsigned b0 = f2tf(Bs[(j * 8 + gid) * KP + d0]);
                unsigned b1 = f2tf(Bs[(j * 8 + gid) * KP + d0 + 4]);
                mma_tf32(o[j], a0, a1, a2, a3, b0, b1);
            }
        }
    }

#pragma unroll
    for (int half = 0; half < 2; half++) {
        int r = row0 + w * 16 + gid + half * 8;
#pragma unroll
        for (int j = 0; j < 8; j++) {
            int cidx = col0 + j * 8 + 2 * t4;
            float2 v;
            v.x = o[j][half * 2]     + bo[cidx];
            v.y = o[j][half * 2 + 1] + bo[cidx + 1];
            *(float2*)(Y + (size_t)r * DM + cidx) = v;
        }
    }
}

// ---------------------------------------------------------------------------
extern "C" void kernel_launch(void* const* d_in, const int* in_sizes, int n_in,
                              void* d_out, int out_size) {
    const float* q  = (const float*)d_in[0];
    const float* k  = (const float*)d_in[1];
    const float* v  = (const float*)d_in[2];
    const float* Wq = (const float*)d_in[3];
    const float* bq = (const float*)d_in[4];
    const float* Wk = (const float*)d_in[5];
    const float* bk = (const float*)d_in[6];
    const float* Wv = (const float*)d_in[7];
    const float* bv = (const float*)d_in[8];
    const float* Wo = (const float*)d_in[9];
    const float* bo = (const float*)d_in[10];
    const int* mask = (const int*)d_in[11];
    float* out = (float*)d_out;

    // 1) QKV projections: 256 row-tiles x 3 matrices
    int qkv_smem = (128 * KP + 64 * KP + 64) * (int)sizeof(float);
    cudaFuncSetAttribute(qkv_proj_kernel,
                         cudaFuncAttributeMaxDynamicSharedMemorySize, qkv_smem);
    qkv_proj_kernel<<<dim3(B * S * H / 128, 3), 256, qkv_smem>>>(
        q, k, v, Wq, bq, Wk, bk, Wv, bv);

    // 2) flash attention: 256 blocks, 2 CTAs/SM
    int attn_smem = (128 * KP + 4 * 64 * KP) * (int)sizeof(float) + 2 * 64 * (int)sizeof(int);
    cudaFuncSetAttribute(attn_kernel,
                         cudaFuncAttributeMaxDynamicSharedMemorySize, attn_smem);
    attn_kernel<<<B * H * (S / 128), 256, attn_smem>>>(mask);

    // 3) output projection: 32 x 8 blocks
    int op_smem = (128 * KP + 64 * KP) * (int)sizeof(float);
    cudaFuncSetAttribute(out_proj_kernel,
                         cudaFuncAttributeMaxDynamicSharedMemorySize, op_smem);
    out_proj_kernel<<<dim3(B * S / 128, DM / 64), 256, op_smem>>>(Wo, bo, out);
}